// round 15
// baseline (speedup 1.0000x reference)
#include <cuda_runtime.h>
#include <math.h>

// ---------------- problem constants ----------------
#define MM   2048
#define NN   2048
#define EE   16384
#define DIN  32
#define HID  64
#define DD   96
#define NHH  4
#define HDD  24
#define FFDD 256
#define LL   4
#define MP1  2049
#define CPLD 2056     // row stride: 2056*4B = 8224 = 32*257 -> 32B-aligned rows
#define SINK_ITERS 100
#define LAMBDA 0.1f
#define AKC   8
#define AKEYS 128

// ---------------- device scratch ----------------
__device__ float g_Cp [(size_t)MP1*CPLD];
__device__ float g_CpT[(size_t)MP1*CPLD];
__device__ float g_P  [(size_t)MP1*CPLD];   // exp(Cp - rmax), pads 0
__device__ float g_QT [(size_t)MP1*CPLD];   // exp(CpT - cmax), pads 0
__device__ float g_rmax[MP1];
__device__ float g_cmax[MP1];
__device__ float g_t    [MM*DD];
__device__ float g_qkv  [MM*3*DD];
__device__ float g_attno[MM*DD];
__device__ float g_attp [(size_t)AKC*MM*DD];
__device__ float g_attlp[AKC*MM*NHH];
__device__ float g_proj [MM*DD];
__device__ float g_ff1  [MM*FFDD];
__device__ float g_cg   [MM*DD];
__device__ float g_match[MM*DD];
__device__ float g_agg  [MM*HID];
__device__ float g_h    [MM*HID];
__device__ float g_deg[MM];
__device__ float g_nrm[MM];
__device__ float g_eu[CPLD];
__device__ float g_ev[CPLD];
__device__ float g_emu[MP1];
__device__ float g_emv[MP1];
__device__ float g_lmmu[MP1];
__device__ float g_lmmv[MP1];
__device__ float g_u[MP1];
__device__ float g_v[MP1];
__device__ float g_v0[MM];
__device__ float g_v1[NN];
__device__ int   g_i0[MM];
__device__ int   g_i1[NN];
__device__ float g_ms0[MM];

// ---------------- helpers ----------------
__device__ __forceinline__ void fma2(unsigned long long& d, unsigned long long a, unsigned long long b) {
    asm("fma.rn.f32x2 %0, %1, %2, %0;" : "+l"(d) : "l"(a), "l"(b));
}
__device__ __forceinline__ float2 unpack2(unsigned long long a) {
    float2 r;
    asm("mov.b64 {%0, %1}, %2;" : "=f"(r.x), "=f"(r.y) : "l"(a));
    return r;
}
__device__ __forceinline__ unsigned long long pack2(float lo, float hi) {
    unsigned long long r;
    asm("mov.b64 %0, {%1, %2};" : "=l"(r) : "f"(lo), "f"(hi));
    return r;
}
// 32B evict_last load (requires 32B alignment)
__device__ __forceinline__ void ld_el8(const float* p, float4& a, float4& b) {
    asm volatile("ld.global.L2::evict_last.v8.b32 {%0,%1,%2,%3,%4,%5,%6,%7}, [%8];"
                 : "=f"(a.x), "=f"(a.y), "=f"(a.z), "=f"(a.w),
                   "=f"(b.x), "=f"(b.y), "=f"(b.z), "=f"(b.w)
                 : "l"(p));
}

// ---------------- GEMM (big tiles: 128x64) ----------------
__global__ void __launch_bounds__(256) gemm_kernel(const float* __restrict__ A,
                                                   const float* __restrict__ B,
                                                   const float* __restrict__ bias,
                                                   float* __restrict__ C,
                                                   int Mm, int Nn, int Kk, int ldc,
                                                   int transB, int mode, float alpha)
{
    __shared__ float As[16][128];
    __shared__ float Bs[16][64];
    int tid = threadIdx.x;
    int m0 = blockIdx.y * 128, n0 = blockIdx.x * 64;
    int tm = tid >> 4, tn = tid & 15;
    float acc[8][4] = {};

    for (int k0 = 0; k0 < Kk; k0 += 16) {
        #pragma unroll
        for (int r = 0; r < 2; r++) {
            int i4 = tid + r * 256;
            int row = i4 >> 2, c4 = (i4 & 3) << 2;
            int gm = m0 + row;
            float4 v = make_float4(0.f, 0.f, 0.f, 0.f);
            if (gm < Mm) v = *(const float4*)(A + (size_t)gm * Kk + k0 + c4);
            As[c4+0][row] = v.x; As[c4+1][row] = v.y; As[c4+2][row] = v.z; As[c4+3][row] = v.w;
        }
        if (!transB) {
            int i4 = tid;
            int row = i4 >> 2, c4 = (i4 & 3) << 2;
            int gn = n0 + row;
            float4 v = make_float4(0.f, 0.f, 0.f, 0.f);
            if (gn < Nn) v = *(const float4*)(B + (size_t)gn * Kk + k0 + c4);
            Bs[c4+0][row] = v.x; Bs[c4+1][row] = v.y; Bs[c4+2][row] = v.z; Bs[c4+3][row] = v.w;
        } else {
            int i4 = tid;
            int brow = i4 >> 4, bc4 = (i4 & 15) << 2;
            int gk = k0 + brow, gn0 = n0 + bc4;
            float4 v;
            if (gn0 + 3 < Nn) {
                v = *(const float4*)(B + (size_t)gk * Nn + gn0);
            } else {
                v.x = (gn0+0 < Nn) ? B[(size_t)gk * Nn + gn0+0] : 0.f;
                v.y = (gn0+1 < Nn) ? B[(size_t)gk * Nn + gn0+1] : 0.f;
                v.z = (gn0+2 < Nn) ? B[(size_t)gk * Nn + gn0+2] : 0.f;
                v.w = (gn0+3 < Nn) ? B[(size_t)gk * Nn + gn0+3] : 0.f;
            }
            Bs[brow][bc4+0] = v.x; Bs[brow][bc4+1] = v.y; Bs[brow][bc4+2] = v.z; Bs[brow][bc4+3] = v.w;
        }
        __syncthreads();
        #pragma unroll
        for (int kk = 0; kk < 16; kk++) {
            float4 al = *(const float4*)&As[kk][tm*8];
            float4 ah = *(const float4*)&As[kk][tm*8+4];
            float4 b  = *(const float4*)&Bs[kk][tn*4];
            float a[8] = {al.x, al.y, al.z, al.w, ah.x, ah.y, ah.z, ah.w};
            float bb[4] = {b.x, b.y, b.z, b.w};
            #pragma unroll
            for (int i = 0; i < 8; i++)
                #pragma unroll
                for (int j = 0; j < 4; j++)
                    acc[i][j] += a[i] * bb[j];
        }
        __syncthreads();
    }
    #pragma unroll
    for (int i = 0; i < 8; i++) {
        int gm = m0 + tm*8 + i;
        if (gm >= Mm) continue;
        #pragma unroll
        for (int j = 0; j < 4; j++) {
            int gn = n0 + tn*4 + j;
            if (gn >= Nn) continue;
            float v = acc[i][j] * alpha;
            if (bias) v += bias[gn];
            if (mode == 1) v = fmaxf(v, 0.f);
            else if (mode == 2) v = fabsf(v);
            C[(size_t)gm * ldc + gn] = v;
        }
    }
}

// ---------------- GEMM small (32x32 tiles, skinny N -> full-chip block count) ----------------
__global__ void __launch_bounds__(256) gemm_small(const float* __restrict__ A,
                                                  const float* __restrict__ B,
                                                  const float* __restrict__ bias,
                                                  float* __restrict__ C,
                                                  int Mm, int Nn, int Kk, int ldc,
                                                  int transB, int mode, float alpha)
{
    __shared__ float As[16][32];
    __shared__ float Bs[16][33];
    int tid = threadIdx.x;
    int m0 = blockIdx.y * 32, n0 = blockIdx.x * 32;
    int tm = tid >> 4, tn = tid & 15;
    float acc[2][2] = {};

    for (int k0 = 0; k0 < Kk; k0 += 16) {
        if (tid < 128) {
            int row = tid >> 2, c4 = (tid & 3) << 2;
            float4 v = *(const float4*)(A + (size_t)(m0 + row) * Kk + k0 + c4);
            As[c4+0][row] = v.x; As[c4+1][row] = v.y; As[c4+2][row] = v.z; As[c4+3][row] = v.w;
        } else {
            int i4 = tid - 128;
            if (!transB) {
                int row = i4 >> 2, c4 = (i4 & 3) << 2;
                float4 v = *(const float4*)(B + (size_t)(n0 + row) * Kk + k0 + c4);
                Bs[c4+0][row] = v.x; Bs[c4+1][row] = v.y; Bs[c4+2][row] = v.z; Bs[c4+3][row] = v.w;
            } else {
                int brow = i4 >> 3, bc4 = (i4 & 7) << 2;
                float4 v = *(const float4*)(B + (size_t)(k0 + brow) * Nn + n0 + bc4);
                Bs[brow][bc4+0] = v.x; Bs[brow][bc4+1] = v.y; Bs[brow][bc4+2] = v.z; Bs[brow][bc4+3] = v.w;
            }
        }
        __syncthreads();
        #pragma unroll
        for (int kk = 0; kk < 16; kk++) {
            float a0 = As[kk][tm*2], a1 = As[kk][tm*2+1];
            float b0 = Bs[kk][tn*2], b1 = Bs[kk][tn*2+1];
            acc[0][0] += a0*b0; acc[0][1] += a0*b1;
            acc[1][0] += a1*b0; acc[1][1] += a1*b1;
        }
        __syncthreads();
    }
    #pragma unroll
    for (int i = 0; i < 2; i++) {
        int gm = m0 + tm*2 + i;
        #pragma unroll
        for (int j = 0; j < 2; j++) {
            int gn = n0 + tn*2 + j;
            float v = acc[i][j] * alpha;
            if (bias) v += bias[gn];
            if (mode == 1) v = fmaxf(v, 0.f);
            else if (mode == 2) v = fabsf(v);
            C[(size_t)gm * ldc + gn] = v;
        }
    }
}

// ---------------- attention v2 ----------------
__global__ void __launch_bounds__(256) attn2_kernel(const float* __restrict__ qkv,
                                                    float* __restrict__ op,
                                                    float* __restrict__ lp)
{
    __shared__ float4 sKV[AKEYS*12];
    int kc = blockIdx.x, head = blockIdx.y, qb = blockIdx.z;
    int tid = threadIdx.x, warp = tid >> 5, lane = tid & 31;

    int qi = qb*256 + warp*32 + lane;
    const unsigned long long* q8 = (const unsigned long long*)(qkv + (size_t)qi*288 + head*24);
    unsigned long long q2[12];
    #pragma unroll
    for (int i = 0; i < 12; i++) q2[i] = q8[i];

    const unsigned long long* skv = (const unsigned long long*)sKV;
    const float rscale = 0.2041241452319315f;
    unsigned long long o2[12];
    #pragma unroll
    for (int i = 0; i < 12; i++) o2[i] = 0ull;
    float l = 0.f;

    for (int st = 0; st < 2048/(AKC*AKEYS); st++) {
        int key0 = kc*(2048/AKC) + st*AKEYS;
        __syncthreads();
        for (int f = tid; f < AKEYS*12; f += 256) {
            int key = f / 12, part = f % 12;
            int base = (part < 6) ? 96 : 192;
            int c4 = part % 6;
            sKV[f] = *(const float4*)(qkv + (size_t)(key0 + key)*288 + base + head*24 + c4*4);
        }
        __syncthreads();
        for (int key = 0; key < AKEYS; key++) {
            const unsigned long long* kk = skv + key*24;
            unsigned long long a0 = 0ull, a1 = 0ull, a2 = 0ull;
            #pragma unroll
            for (int c = 0; c < 12; c += 3) {
                fma2(a0, q2[c+0], kk[c+0]);
                fma2(a1, q2[c+1], kk[c+1]);
                fma2(a2, q2[c+2], kk[c+2]);
            }
            float2 f0 = unpack2(a0), f1 = unpack2(a1), f2 = unpack2(a2);
            float s = (f0.x + f0.y) + (f1.x + f1.y) + (f2.x + f2.y);
            float p = __expf(s * rscale);
            l += p;
            unsigned long long p2 = pack2(p, p);
            #pragma unroll
            for (int c = 0; c < 12; c++) fma2(o2[c], p2, kk[12 + c]);
        }
    }

    unsigned long long* od = (unsigned long long*)(op + ((size_t)kc*MM + qi)*96 + head*24);
    #pragma unroll
    for (int c = 0; c < 12; c++) od[c] = o2[c];
    lp[(kc*MM + qi)*NHH + head] = l;
}

__global__ void attn2_norm(const float* __restrict__ op, const float* __restrict__ lp,
                           float* __restrict__ out)
{
    int qi = blockIdx.x, c = threadIdx.x;
    int head = c / 24;
    float so = 0.f, sl = 0.f;
    #pragma unroll
    for (int kc = 0; kc < AKC; kc++) {
        so += op[((size_t)kc*MM + qi)*96 + c];
        sl += lp[(kc*MM + qi)*NHH + head];
    }
    out[(size_t)qi*96 + c] = so / sl;
}

// ---------------- LayerNorm ----------------
__global__ void ln_kernel(float* __restrict__ t, const float* __restrict__ delta,
                          const float* __restrict__ g, const float* __restrict__ b)
{
    __shared__ float sr[96];
    int i = blockIdx.x, c = threadIdx.x;
    float x = t[(size_t)i*96 + c] + delta[(size_t)i*96 + c];
    sr[c] = x;
    __syncthreads();
    for (int s = 64; s > 0; s >>= 1) { if (c < s && c + s < 96) sr[c] += sr[c+s]; __syncthreads(); }
    float mu = sr[0] / 96.f;
    __syncthreads();
    float d = x - mu;
    sr[c] = d * d;
    __syncthreads();
    for (int s = 64; s > 0; s >>= 1) { if (c < s && c + s < 96) sr[c] += sr[c+s]; __syncthreads(); }
    float var = sr[0] / 96.f;
    t[(size_t)i*96 + c] = d * rsqrtf(var + 1e-5f) * g[c] + b[c];
}

// ---------------- GCN propagation ----------------
__global__ void k_deg_init() { int i = blockIdx.x*blockDim.x + threadIdx.x; if (i < MM) g_deg[i] = 1.f; }
__global__ void k_deg_acc(const int* __restrict__ ei) {
    int e = blockIdx.x*blockDim.x + threadIdx.x;
    if (e < EE) atomicAdd(&g_deg[ei[EE + e]], 1.f);
}
__global__ void k_nrm() { int i = blockIdx.x*blockDim.x + threadIdx.x; if (i < MM) g_nrm[i] = rsqrtf(g_deg[i]); }
__global__ void k_prop_init(const float* __restrict__ h, int F) {
    int idx = blockIdx.x*blockDim.x + threadIdx.x;
    if (idx < MM * F) g_agg[idx] = h[idx] * g_nrm[idx / F];
}
__global__ void k_prop_edge(const float* __restrict__ h, const int* __restrict__ ei, int F) {
    int idx = blockIdx.x*blockDim.x + threadIdx.x;
    if (idx < EE * F) {
        int e = idx / F, f = idx % F;
        int s = ei[e], d = ei[EE + e];
        atomicAdd(&g_agg[(size_t)d * F + f], h[(size_t)s * F + f] * g_nrm[s]);
    }
}
__global__ void k_prop_scale(int F) {
    int idx = blockIdx.x*blockDim.x + threadIdx.x;
    if (idx < MM * F) g_agg[idx] *= g_nrm[idx / F];
}

// ---------------- Sinkhorn setup ----------------
__global__ void k_bins(const float* __restrict__ binp) {
    int i = blockIdx.x*blockDim.x + threadIdx.x;
    if (i < MP1) {
        float bl = binp[0] / LAMBDA;
        g_Cp[(size_t)i*CPLD + (MP1-1)] = bl;
        g_Cp[(size_t)(MP1-1)*CPLD + i] = bl;
    }
}
__global__ void transpose_kernel() {
    __shared__ float tile[32][33];
    int bx = blockIdx.x * 32, by = blockIdx.y * 32;
    int tx = threadIdx.x, ty = threadIdx.y;
    #pragma unroll
    for (int r = 0; r < 32; r += 8) {
        int y = by + ty + r, x = bx + tx;
        if (y < MP1 && x < MP1) tile[ty + r][tx] = g_Cp[(size_t)y*CPLD + x];
    }
    __syncthreads();
    #pragma unroll
    for (int r = 0; r < 32; r += 8) {
        int y = bx + ty + r, x = by + tx;
        if (y < MP1 && x < MP1) g_CpT[(size_t)y*CPLD + x] = tile[tx][ty + r];
    }
}
__global__ void rowmax_kernel(const float* __restrict__ Mx, float* __restrict__ out) {
    int wid = threadIdx.x >> 5, lane = threadIdx.x & 31;
    int r = blockIdx.x * 8 + wid;
    if (r >= MP1) return;
    const float4* row = (const float4*)(Mx + (size_t)r * CPLD);
    float m = -1e30f;
    #pragma unroll
    for (int k0 = 0; k0 < 16; k0++) {
        float4 a = row[lane + 32*k0];
        m = fmaxf(m, fmaxf(fmaxf(a.x, a.y), fmaxf(a.z, a.w)));
    }
    if (lane == 0) m = fmaxf(m, Mx[(size_t)r*CPLD + 2048]);
    #pragma unroll
    for (int off = 16; off; off >>= 1) m = fmaxf(m, __shfl_xor_sync(0xffffffffu, m, off));
    if (lane == 0) out[r] = m;
}
__global__ void expsub_kernel(const float* __restrict__ Mx, const float* __restrict__ mx,
                              float* __restrict__ P) {
    int j = blockIdx.x * 256 + threadIdx.x;
    int r = blockIdx.y;
    if (j < CPLD)
        P[(size_t)r*CPLD + j] = (j < MP1) ? __expf(Mx[(size_t)r*CPLD + j] - mx[r]) : 0.f;
}
__global__ void k_sink_init() {
    int i = blockIdx.x*blockDim.x + threadIdx.x;
    if (i < CPLD) {
        float norm = -logf((float)(MM + NN));
        bool pad = (i >= MP1);
        g_eu[i] = pad ? 0.f : 1.f;
        g_ev[i] = pad ? 0.f : 1.f;
        if (!pad) {
            float lmu = (i < MM) ? norm : (logf((float)NN) + norm);
            float lnu = (i < NN) ? norm : (logf((float)MM) + norm);
            float a = lmu - g_rmax[i];
            float b = lnu - g_cmax[i];
            g_lmmu[i] = a; g_emu[i] = __expf(a);
            g_lmmv[i] = b; g_emv[i] = __expf(b);
            g_u[i] = 0.f; g_v[i] = 0.f;
        }
    }
}

// ---------------- Sinkhorn GEMV v6: warp-per-row, ALL row loads front-batched ----------------
// 257 blocks x 256 thr. Row = 257 chunks of 8 floats; lane handles chunks lane+32c.
__global__ void __launch_bounds__(256, 1) gemv5(const float* __restrict__ Pm,
                                                const float* __restrict__ evin,
                                                const float* __restrict__ emarg,
                                                const float* __restrict__ lmm,
                                                float* __restrict__ evout,
                                                float* __restrict__ logout)
{
    __shared__ float sev[CPLD];
    int tid = threadIdx.x, lane = tid & 31, warp = tid >> 5;
    for (int i = tid; i < CPLD/4; i += 256)
        ((float4*)sev)[i] = ((const float4*)evin)[i];
    __syncthreads();

    int r = blockIdx.x * 8 + warp;
    if (r >= MP1) return;
    const float* rowp = Pm + (size_t)r * CPLD;
    const float4* sev4 = (const float4*)sev;

    // front-batch: issue all 8 x 32B loads back-to-back (one latency exposure)
    float4 p[16];
    #pragma unroll
    for (int c = 0; c < 8; c++)
        ld_el8(rowp + (lane + 32*c)*8, p[2*c], p[2*c+1]);
    float4 qa, qb;
    if (lane == 0) ld_el8(rowp + 2048, qa, qb);   // chunk 256 (cols 2048..2055, pads 0)

    float a0 = 0.f, a1 = 0.f, a2 = 0.f, a3 = 0.f;
    #pragma unroll
    for (int c = 0; c < 8; c += 2) {
        int ch0 = lane + 32*c, ch1 = lane + 32*(c+1);
        float4 e0 = sev4[ch0*2],   e1 = sev4[ch0*2+1];
        float4 e2 = sev4[ch1*2],   e3 = sev4[ch1*2+1];
        a0 += p[2*c+0].x*e0.x + p[2*c+0].y*e0.y + p[2*c+0].z*e0.z + p[2*c+0].w*e0.w;
        a1 += p[2*c+1].x*e1.x + p[2*c+1].y*e1.y + p[2*c+1].z*e1.z + p[2*c+1].w*e1.w;
        a2 += p[2*c+2].x*e2.x + p[2*c+2].y*e2.y + p[2*c+2].z*e2.z + p[2*c+2].w*e2.w;
        a3 += p[2*c+3].x*e3.x + p[2*c+3].y*e3.y + p[2*c+3].z*e3.z + p[2*c+3].w*e3.w;
    }
    if (lane == 0) {
        float4 f0 = sev4[512], f1 = sev4[513];
        a0 += qa.x*f0.x + qa.y*f0.y + qa.z*f0.z + qa.w*f0.w
            + qb.x*f1.x + qb.y*f1.y + qb.z*f1.z + qb.w*f1.w;
    }
    float acc = (a0 + a1) + (a2 + a3);
    #pragma unroll
    for (int off = 16; off; off >>= 1) acc += __shfl_xor_sync(0xffffffffu, acc, off);
    if (lane == 0) {
        evout[r]  = emarg[r] / acc;
        logout[r] = lmm[r] - __logf(acc);
    }
}

// ---------------- outputs ----------------
__global__ void __launch_bounds__(256) k_scores_row(float* __restrict__ out,
                                                    float* __restrict__ ent_out)
{
    __shared__ float sv[256]; __shared__ int si[256]; __shared__ float se[256];
    int i = blockIdx.x, tid = threadIdx.x;
    const float norm = -8.317766166719343f;
    float ui = g_u[i];
    bool dorow = (i < MM);
    float bv = -1e30f; int bi = 0; float ent = 0.f;
    for (int j = tid; j < MP1; j += 256) {
        float x = g_Cp[(size_t)i*CPLD + j] + ui + g_v[j] - norm;
        out[(size_t)i*MP1 + j] = x;
        if (dorow && j < NN) {
            if (x > bv) { bv = x; bi = j; }
            ent += x * __expf(x);
        }
    }
    if (!dorow) return;
    sv[tid] = bv; si[tid] = bi; se[tid] = ent; __syncthreads();
    for (int s = 128; s > 0; s >>= 1) {
        if (tid < s) {
            if (sv[tid+s] > sv[tid] || (sv[tid+s] == sv[tid] && si[tid+s] < si[tid])) {
                sv[tid] = sv[tid+s]; si[tid] = si[tid+s];
            }
            se[tid] += se[tid+s];
        }
        __syncthreads();
    }
    if (tid == 0) { g_v0[i] = sv[0]; g_i0[i] = si[0]; ent_out[i] = se[0]; }
}
__global__ void k_colstat() {
    __shared__ float sv[256]; __shared__ int si[256];
    int j = blockIdx.x, tid = threadIdx.x;
    const float norm = -8.317766166719343f;
    float vj = g_v[j];
    float bv = -1e30f; int bi = 0;
    for (int i = tid; i < MM; i += 256) {
        float x = g_CpT[(size_t)j*CPLD + i] + g_u[i] + vj - norm;
        if (x > bv) { bv = x; bi = i; }
    }
    sv[tid] = bv; si[tid] = bi; __syncthreads();
    for (int s = 128; s > 0; s >>= 1) {
        if (tid < s) {
            if (sv[tid+s] > sv[tid] || (sv[tid+s] == sv[tid] && si[tid+s] < si[tid])) {
                sv[tid] = sv[tid+s]; si[tid] = si[tid+s];
            }
        }
        __syncthreads();
    }
    if (tid == 0) { g_v1[j] = sv[0]; g_i1[j] = si[0]; }
}
__global__ void k_mutual0(float* __restrict__ ms0_out) {
    int i = blockIdx.x*blockDim.x + threadIdx.x;
    if (i < MM) {
        int j = g_i0[i];
        float val = (g_i1[j] == i) ? __expf(g_v0[i]) : 0.f;
        g_ms0[i] = val;
        ms0_out[i] = val;
    }
}
__global__ void k_mutual1(float* __restrict__ ms1_out) {
    int j = blockIdx.x*blockDim.x + threadIdx.x;
    if (j < NN) {
        int i = g_i1[j];
        ms1_out[j] = (g_i0[i] == j) ? g_ms0[i] : 0.f;
    }
}

// ---------------- host side ----------------
static float* sym(const void* p) { return (float*)p; }

extern "C" void kernel_launch(void* const* d_in, const int* in_sizes, int n_in,
                              void* d_out, int out_size)
{
    const float* x        = (const float*)d_in[0];
    const int*   ei       = (const int*)  d_in[1];
    const float* devfeat  = (const float*)d_in[2];
    const float* gnn_w1   = (const float*)d_in[3];
    const float* gnn_b1   = (const float*)d_in[4];
    const float* gnn_w2   = (const float*)d_in[5];
    const float* gnn_b2   = (const float*)d_in[6];
    const float* sa_w     = (const float*)d_in[7];
    const float* sa_b     = (const float*)d_in[8];
    const float* sa_ow    = (const float*)d_in[9];
    const float* sa_ob    = (const float*)d_in[10];
    const float* ca_w     = (const float*)d_in[11];
    const float* ca_b     = (const float*)d_in[12];
    const float* ca_ow    = (const float*)d_in[13];
    const float* ca_ob    = (const float*)d_in[14];
    const float* ln_g     = (const float*)d_in[15];
    const float* ln_b     = (const float*)d_in[16];
    const float* ff_w1    = (const float*)d_in[17];
    const float* ff_b1    = (const float*)d_in[18];
    const float* ff_w2    = (const float*)d_in[19];
    const float* ff_b2    = (const float*)d_in[20];
    const float* mf_w     = (const float*)d_in[21];
    const float* mf_b     = (const float*)d_in[22];
    const float* bin      = (const float*)d_in[23];
    float* out = (float*)d_out;

    void *pv;
    cudaGetSymbolAddress(&pv, g_Cp);    float* p_Cp    = sym(pv);
    cudaGetSymbolAddress(&pv, g_CpT);   float* p_CpT   = sym(pv);
    cudaGetSymbolAddress(&pv, g_P);     float* p_P     = sym(pv);
    cudaGetSymbolAddress(&pv, g_QT);    float* p_QT    = sym(pv);
    cudaGetSymbolAddress(&pv, g_rmax);  float* p_rmax  = sym(pv);
    cudaGetSymbolAddress(&pv, g_cmax);  float* p_cmax  = sym(pv);
    cudaGetSymbolAddress(&pv, g_t);     float* p_t     = sym(pv);
    cudaGetSymbolAddress(&pv, g_qkv);   float* p_qkv   = sym(pv);
    cudaGetSymbolAddress(&pv, g_attno); float* p_attno = sym(pv);
    cudaGetSymbolAddress(&pv, g_attp);  float* p_attp  = sym(pv);
    cudaGetSymbolAddress(&pv, g_attlp); float* p_attlp = sym(pv);
    cudaGetSymbolAddress(&pv, g_proj);  float* p_proj  = sym(pv);
    cudaGetSymbolAddress(&pv, g_ff1);   float* p_ff1   = sym(pv);
    cudaGetSymbolAddress(&pv, g_cg);    float* p_cg    = sym(pv);
    cudaGetSymbolAddress(&pv, g_match); float* p_match = sym(pv);
    cudaGetSymbolAddress(&pv, g_agg);   float* p_agg   = sym(pv);
    cudaGetSymbolAddress(&pv, g_h);     float* p_h     = sym(pv);
    cudaGetSymbolAddress(&pv, g_eu);    float* p_eu    = sym(pv);
    cudaGetSymbolAddress(&pv, g_ev);    float* p_ev    = sym(pv);
    cudaGetSymbolAddress(&pv, g_emu);   float* p_emu   = sym(pv);
    cudaGetSymbolAddress(&pv, g_emv);   float* p_emv   = sym(pv);
    cudaGetSymbolAddress(&pv, g_lmmu);  float* p_lmmu  = sym(pv);
    cudaGetSymbolAddress(&pv, g_lmmv);  float* p_lmmv  = sym(pv);
    cudaGetSymbolAddress(&pv, g_u);     float* p_u     = sym(pv);
    cudaGetSymbolAddress(&pv, g_v);     float* p_v     = sym(pv);

    auto gemm = [&](const float* A, const float* B, const float* bias, float* C,
                    int Mm, int Nn, int Kk, int ldc, int transB, int mode, float alpha) {
        if (Nn <= 512 && (Mm % 32) == 0 && (Nn % 32) == 0) {
            dim3 grid(Nn / 32, Mm / 32);
            gemm_small<<<grid, 256>>>(A, B, bias, C, Mm, Nn, Kk, ldc, transB, mode, alpha);
        } else {
            dim3 grid((Nn + 63) / 64, (Mm + 127) / 128);
            gemm_kernel<<<grid, 256>>>(A, B, bias, C, Mm, Nn, Kk, ldc, transB, mode, alpha);
        }
    };

    int sgrid = (MP1 + 7) / 8;   // 257 blocks

    // ---- ncu probes (profiled launch = gemv5; state re-initialized later) ----
    for (int p = 0; p < 8; p++)
        gemv5<<<sgrid, 256>>>(p_P, p_ev, p_emu, p_lmmu, p_eu, p_u);

    // ---- GCN ----
    k_deg_init<<<(MM+255)/256, 256>>>();
    k_deg_acc<<<(EE+255)/256, 256>>>(ei);
    k_nrm<<<(MM+255)/256, 256>>>();

    k_prop_init <<<(MM*DIN+255)/256, 256>>>(x, DIN);
    k_prop_edge <<<(EE*DIN+255)/256, 256>>>(x, ei, DIN);
    k_prop_scale<<<(MM*DIN+255)/256, 256>>>(DIN);
    gemm(p_agg, gnn_w1, gnn_b1, p_h, MM, HID, DIN, HID, 1, 0, 1.f);

    k_prop_init <<<(MM*HID+255)/256, 256>>>(p_h, HID);
    k_prop_edge <<<(EE*HID+255)/256, 256>>>(p_h, ei, HID);
    k_prop_scale<<<(MM*HID+255)/256, 256>>>(HID);
    gemm(p_agg, gnn_w2, gnn_b2, p_cg, MM, DD, HID, DD, 1, 0, 1.f);

    // ---- transformer ----
    cudaMemcpyAsync(p_t, devfeat, (size_t)MM*DD*sizeof(float), cudaMemcpyDeviceToDevice);
    dim3 agrid(AKC, NHH, MM/256);
    for (int l = 0; l < LL; l++) {
        gemm(p_t, sa_w + (size_t)l*288*96, sa_b + l*288, p_qkv, MM, 288, 96, 288, 0, 0, 1.f);
        attn2_kernel<<<agrid, 256>>>(p_qkv, p_attp, p_attlp);
        attn2_norm<<<MM, 96>>>(p_attp, p_attlp, p_attno);
        gemm(p_attno, sa_ow + (size_t)l*96*96, sa_ob + l*96, p_proj, MM, 96, 96, 96, 0, 0, 1.f);
        ln_kernel<<<MM, 96>>>(p_t, p_proj, ln_g + (l*3+0)*96, ln_b + (l*3+0)*96);
        gemm(p_t,  ca_w + (size_t)l*288*96,         ca_b + l*288,      p_qkv,      MM,  96, 96, 288, 0, 0, 1.f);
        gemm(p_cg, ca_w + (size_t)l*288*96 + 96*96, ca_b + l*288 + 96, p_qkv + 96, MM, 192, 96, 288, 0, 0, 1.f);
        attn2_kernel<<<agrid, 256>>>(p_qkv, p_attp, p_attlp);
        attn2_norm<<<MM, 96>>>(p_attp, p_attlp, p_attno);
        gemm(p_attno, ca_ow + (size_t)l*96*96, ca_ob + l*96, p_proj, MM, 96, 96, 96, 0, 0, 1.f);
        ln_kernel<<<MM, 96>>>(p_t, p_proj, ln_g + (l*3+1)*96, ln_b + (l*3+1)*96);
        gemm(p_t,   ff_w1 + (size_t)l*256*96, ff_b1 + l*256, p_ff1,  MM, 256,  96, 256, 0, 1, 1.f);
        gemm(p_ff1, ff_w2 + (size_t)l*96*256, ff_b2 + l*96,  p_proj, MM,  96, 256,  96, 0, 0, 1.f);
        ln_kernel<<<MM, 96>>>(p_t, p_proj, ln_g + (l*3+2)*96, ln_b + (l*3+2)*96);
    }

    // ---- cost matrix + bins + transpose + exp-precompute ----
    gemm(p_t, mf_w, mf_b, p_match, MM, 96, 96, 96, 1, 0, 1.f);
    float alpha = 1.f / (sqrtf(96.f) * LAMBDA);
    gemm(p_cg, p_match, 0, p_Cp, MM, NN, 96, CPLD, 0, 2, alpha);
    k_bins<<<(MP1+255)/256, 256>>>(bin);
    transpose_kernel<<<dim3(65, 65), dim3(32, 8)>>>();
    rowmax_kernel<<<(MP1+7)/8, 256>>>(p_Cp,  p_rmax);
    rowmax_kernel<<<(MP1+7)/8, 256>>>(p_CpT, p_cmax);
    expsub_kernel<<<dim3((CPLD+255)/256, MP1), 256>>>(p_Cp,  p_rmax, p_P);
    expsub_kernel<<<dim3((CPLD+255)/256, MP1), 256>>>(p_CpT, p_cmax, p_QT);
    k_sink_init<<<(CPLD+255)/256, 256>>>();

    // ---- Sinkhorn ----
    for (int it = 0; it < SINK_ITERS; it++) {
        gemv5<<<sgrid, 256>>>(p_P,  p_ev, p_emu, p_lmmu, p_eu, p_u);
        gemv5<<<sgrid, 256>>>(p_QT, p_eu, p_emv, p_lmmv, p_ev, p_v);
    }

    // ---- outputs ----
    size_t off_ent = (size_t)MP1 * MP1;
    k_scores_row<<<MP1, 256>>>(out, out + off_ent);
    k_colstat<<<NN, 256>>>();
    k_mutual0<<<(MM+255)/256, 256>>>(out + off_ent + MM);
    k_mutual1<<<(NN+255)/256, 256>>>(out + off_ent + MM + NN);
}

// round 16
// speedup vs baseline: 1.0173x; 1.0173x over previous
#include <cuda_runtime.h>
#include <math.h>

// ---------------- problem constants ----------------
#define MM   2048
#define NN   2048
#define EE   16384
#define DIN  32
#define HID  64
#define DD   96
#define NHH  4
#define HDD  24
#define FFDD 256
#define LL   4
#define MP1  2049
#define CPLD 2056     // row stride: 2056*4B = 8224 = 16*514 (bulk-copy friendly)
#define SINK_ITERS 100
#define LAMBDA 0.1f
#define AKC   8
#define AKEYS 128
#define G6_SMEM (9*CPLD*4 + 16)   // 8 rows + ev + mbarrier

// ---------------- device scratch ----------------
__device__ float g_Cp [(size_t)MP1*CPLD];
__device__ float g_CpT[(size_t)MP1*CPLD];
__device__ float g_P  [(size_t)MP1*CPLD];   // exp(Cp - rmax), pads 0
__device__ float g_QT [(size_t)MP1*CPLD];   // exp(CpT - cmax), pads 0
__device__ float g_rmax[MP1];
__device__ float g_cmax[MP1];
__device__ float g_t    [MM*DD];
__device__ float g_qkv  [MM*3*DD];
__device__ float g_attno[MM*DD];
__device__ float g_attp [(size_t)AKC*MM*DD];
__device__ float g_attlp[AKC*MM*NHH];
__device__ float g_proj [MM*DD];
__device__ float g_ff1  [MM*FFDD];
__device__ float g_cg   [MM*DD];
__device__ float g_match[MM*DD];
__device__ float g_agg  [MM*HID];
__device__ float g_h    [MM*HID];
__device__ float g_deg[MM];
__device__ float g_nrm[MM];
__device__ float g_eu[CPLD];
__device__ float g_ev[CPLD];
__device__ float g_emu[MP1];
__device__ float g_emv[MP1];
__device__ float g_lmmu[MP1];
__device__ float g_lmmv[MP1];
__device__ float g_u[MP1];
__device__ float g_v[MP1];
__device__ float g_v0[MM];
__device__ float g_v1[NN];
__device__ int   g_i0[MM];
__device__ int   g_i1[NN];
__device__ float g_ms0[MM];

// ---------------- helpers ----------------
__device__ __forceinline__ void fma2(unsigned long long& d, unsigned long long a, unsigned long long b) {
    asm("fma.rn.f32x2 %0, %1, %2, %0;" : "+l"(d) : "l"(a), "l"(b));
}
__device__ __forceinline__ float2 unpack2(unsigned long long a) {
    float2 r;
    asm("mov.b64 {%0, %1}, %2;" : "=f"(r.x), "=f"(r.y) : "l"(a));
    return r;
}
__device__ __forceinline__ unsigned long long pack2(float lo, float hi) {
    unsigned long long r;
    asm("mov.b64 %0, {%1, %2};" : "=l"(r) : "f"(lo), "f"(hi));
    return r;
}
__device__ __forceinline__ unsigned smem_u32(const void* p) {
    unsigned a;
    asm("{ .reg .u64 t; cvta.to.shared.u64 t, %1; cvt.u32.u64 %0, t; }" : "=r"(a) : "l"(p));
    return a;
}
__device__ __forceinline__ void bulk_g2s(unsigned dst, const void* src, unsigned bytes, unsigned mbar) {
    asm volatile("cp.async.bulk.shared::cta.global.mbarrier::complete_tx::bytes [%0], [%1], %2, [%3];"
                 :: "r"(dst), "l"(src), "r"(bytes), "r"(mbar) : "memory");
}
__device__ __forceinline__ void mbar_init(unsigned mbar, unsigned cnt) {
    asm volatile("mbarrier.init.shared.b64 [%0], %1;" :: "r"(mbar), "r"(cnt) : "memory");
}
__device__ __forceinline__ void mbar_expect(unsigned mbar, unsigned bytes) {
    asm volatile("mbarrier.arrive.expect_tx.shared.b64 _, [%0], %1;" :: "r"(mbar), "r"(bytes) : "memory");
}
__device__ __forceinline__ void mbar_wait0(unsigned mbar) {
    asm volatile("{\n\t.reg .pred P;\n"
                 "W1:\n\t"
                 "mbarrier.try_wait.parity.acquire.cta.shared::cta.b64 P, [%0], 0;\n\t"
                 "@!P bra W1;\n\t}"
                 :: "r"(mbar) : "memory");
}

// ---------------- GEMM (big tiles: 128x64) ----------------
__global__ void __launch_bounds__(256) gemm_kernel(const float* __restrict__ A,
                                                   const float* __restrict__ B,
                                                   const float* __restrict__ bias,
                                                   float* __restrict__ C,
                                                   int Mm, int Nn, int Kk, int ldc,
                                                   int transB, int mode, float alpha)
{
    __shared__ float As[16][128];
    __shared__ float Bs[16][64];
    int tid = threadIdx.x;
    int m0 = blockIdx.y * 128, n0 = blockIdx.x * 64;
    int tm = tid >> 4, tn = tid & 15;
    float acc[8][4] = {};

    for (int k0 = 0; k0 < Kk; k0 += 16) {
        #pragma unroll
        for (int r = 0; r < 2; r++) {
            int i4 = tid + r * 256;
            int row = i4 >> 2, c4 = (i4 & 3) << 2;
            int gm = m0 + row;
            float4 v = make_float4(0.f, 0.f, 0.f, 0.f);
            if (gm < Mm) v = *(const float4*)(A + (size_t)gm * Kk + k0 + c4);
            As[c4+0][row] = v.x; As[c4+1][row] = v.y; As[c4+2][row] = v.z; As[c4+3][row] = v.w;
        }
        if (!transB) {
            int i4 = tid;
            int row = i4 >> 2, c4 = (i4 & 3) << 2;
            int gn = n0 + row;
            float4 v = make_float4(0.f, 0.f, 0.f, 0.f);
            if (gn < Nn) v = *(const float4*)(B + (size_t)gn * Kk + k0 + c4);
            Bs[c4+0][row] = v.x; Bs[c4+1][row] = v.y; Bs[c4+2][row] = v.z; Bs[c4+3][row] = v.w;
        } else {
            int i4 = tid;
            int brow = i4 >> 4, bc4 = (i4 & 15) << 2;
            int gk = k0 + brow, gn0 = n0 + bc4;
            float4 v;
            if (gn0 + 3 < Nn) {
                v = *(const float4*)(B + (size_t)gk * Nn + gn0);
            } else {
                v.x = (gn0+0 < Nn) ? B[(size_t)gk * Nn + gn0+0] : 0.f;
                v.y = (gn0+1 < Nn) ? B[(size_t)gk * Nn + gn0+1] : 0.f;
                v.z = (gn0+2 < Nn) ? B[(size_t)gk * Nn + gn0+2] : 0.f;
                v.w = (gn0+3 < Nn) ? B[(size_t)gk * Nn + gn0+3] : 0.f;
            }
            Bs[brow][bc4+0] = v.x; Bs[brow][bc4+1] = v.y; Bs[brow][bc4+2] = v.z; Bs[brow][bc4+3] = v.w;
        }
        __syncthreads();
        #pragma unroll
        for (int kk = 0; kk < 16; kk++) {
            float4 al = *(const float4*)&As[kk][tm*8];
            float4 ah = *(const float4*)&As[kk][tm*8+4];
            float4 b  = *(const float4*)&Bs[kk][tn*4];
            float a[8] = {al.x, al.y, al.z, al.w, ah.x, ah.y, ah.z, ah.w};
            float bb[4] = {b.x, b.y, b.z, b.w};
            #pragma unroll
            for (int i = 0; i < 8; i++)
                #pragma unroll
                for (int j = 0; j < 4; j++)
                    acc[i][j] += a[i] * bb[j];
        }
        __syncthreads();
    }
    #pragma unroll
    for (int i = 0; i < 8; i++) {
        int gm = m0 + tm*8 + i;
        if (gm >= Mm) continue;
        #pragma unroll
        for (int j = 0; j < 4; j++) {
            int gn = n0 + tn*4 + j;
            if (gn >= Nn) continue;
            float v = acc[i][j] * alpha;
            if (bias) v += bias[gn];
            if (mode == 1) v = fmaxf(v, 0.f);
            else if (mode == 2) v = fabsf(v);
            C[(size_t)gm * ldc + gn] = v;
        }
    }
}

// ---------------- GEMM small (32x32 tiles) ----------------
__global__ void __launch_bounds__(256) gemm_small(const float* __restrict__ A,
                                                  const float* __restrict__ B,
                                                  const float* __restrict__ bias,
                                                  float* __restrict__ C,
                                                  int Mm, int Nn, int Kk, int ldc,
                                                  int transB, int mode, float alpha)
{
    __shared__ float As[16][32];
    __shared__ float Bs[16][33];
    int tid = threadIdx.x;
    int m0 = blockIdx.y * 32, n0 = blockIdx.x * 32;
    int tm = tid >> 4, tn = tid & 15;
    float acc[2][2] = {};

    for (int k0 = 0; k0 < Kk; k0 += 16) {
        if (tid < 128) {
            int row = tid >> 2, c4 = (tid & 3) << 2;
            float4 v = *(const float4*)(A + (size_t)(m0 + row) * Kk + k0 + c4);
            As[c4+0][row] = v.x; As[c4+1][row] = v.y; As[c4+2][row] = v.z; As[c4+3][row] = v.w;
        } else {
            int i4 = tid - 128;
            if (!transB) {
                int row = i4 >> 2, c4 = (i4 & 3) << 2;
                float4 v = *(const float4*)(B + (size_t)(n0 + row) * Kk + k0 + c4);
                Bs[c4+0][row] = v.x; Bs[c4+1][row] = v.y; Bs[c4+2][row] = v.z; Bs[c4+3][row] = v.w;
            } else {
                int brow = i4 >> 3, bc4 = (i4 & 7) << 2;
                float4 v = *(const float4*)(B + (size_t)(k0 + brow) * Nn + n0 + bc4);
                Bs[brow][bc4+0] = v.x; Bs[brow][bc4+1] = v.y; Bs[brow][bc4+2] = v.z; Bs[brow][bc4+3] = v.w;
            }
        }
        __syncthreads();
        #pragma unroll
        for (int kk = 0; kk < 16; kk++) {
            float a0 = As[kk][tm*2], a1 = As[kk][tm*2+1];
            float b0 = Bs[kk][tn*2], b1 = Bs[kk][tn*2+1];
            acc[0][0] += a0*b0; acc[0][1] += a0*b1;
            acc[1][0] += a1*b0; acc[1][1] += a1*b1;
        }
        __syncthreads();
    }
    #pragma unroll
    for (int i = 0; i < 2; i++) {
        int gm = m0 + tm*2 + i;
        #pragma unroll
        for (int j = 0; j < 2; j++) {
            int gn = n0 + tn*2 + j;
            float v = acc[i][j] * alpha;
            if (bias) v += bias[gn];
            if (mode == 1) v = fmaxf(v, 0.f);
            else if (mode == 2) v = fabsf(v);
            C[(size_t)gm * ldc + gn] = v;
        }
    }
}

// ---------------- attention v2 ----------------
__global__ void __launch_bounds__(256) attn2_kernel(const float* __restrict__ qkv,
                                                    float* __restrict__ op,
                                                    float* __restrict__ lp)
{
    __shared__ float4 sKV[AKEYS*12];
    int kc = blockIdx.x, head = blockIdx.y, qb = blockIdx.z;
    int tid = threadIdx.x, warp = tid >> 5, lane = tid & 31;

    int qi = qb*256 + warp*32 + lane;
    const unsigned long long* q8 = (const unsigned long long*)(qkv + (size_t)qi*288 + head*24);
    unsigned long long q2[12];
    #pragma unroll
    for (int i = 0; i < 12; i++) q2[i] = q8[i];

    const unsigned long long* skv = (const unsigned long long*)sKV;
    const float rscale = 0.2041241452319315f;
    unsigned long long o2[12];
    #pragma unroll
    for (int i = 0; i < 12; i++) o2[i] = 0ull;
    float l = 0.f;

    for (int st = 0; st < 2048/(AKC*AKEYS); st++) {
        int key0 = kc*(2048/AKC) + st*AKEYS;
        __syncthreads();
        for (int f = tid; f < AKEYS*12; f += 256) {
            int key = f / 12, part = f % 12;
            int base = (part < 6) ? 96 : 192;
            int c4 = part % 6;
            sKV[f] = *(const float4*)(qkv + (size_t)(key0 + key)*288 + base + head*24 + c4*4);
        }
        __syncthreads();
        for (int key = 0; key < AKEYS; key++) {
            const unsigned long long* kk = skv + key*24;
            unsigned long long a0 = 0ull, a1 = 0ull, a2 = 0ull;
            #pragma unroll
            for (int c = 0; c < 12; c += 3) {
                fma2(a0, q2[c+0], kk[c+0]);
                fma2(a1, q2[c+1], kk[c+1]);
                fma2(a2, q2[c+2], kk[c+2]);
            }
            float2 f0 = unpack2(a0), f1 = unpack2(a1), f2 = unpack2(a2);
            float s = (f0.x + f0.y) + (f1.x + f1.y) + (f2.x + f2.y);
            float p = __expf(s * rscale);
            l += p;
            unsigned long long p2 = pack2(p, p);
            #pragma unroll
            for (int c = 0; c < 12; c++) fma2(o2[c], p2, kk[12 + c]);
        }
    }

    unsigned long long* od = (unsigned long long*)(op + ((size_t)kc*MM + qi)*96 + head*24);
    #pragma unroll
    for (int c = 0; c < 12; c++) od[c] = o2[c];
    lp[(kc*MM + qi)*NHH + head] = l;
}

__global__ void attn2_norm(const float* __restrict__ op, const float* __restrict__ lp,
                           float* __restrict__ out)
{
    int qi = blockIdx.x, c = threadIdx.x;
    int head = c / 24;
    float so = 0.f, sl = 0.f;
    #pragma unroll
    for (int kc = 0; kc < AKC; kc++) {
        so += op[((size_t)kc*MM + qi)*96 + c];
        sl += lp[(kc*MM + qi)*NHH + head];
    }
    out[(size_t)qi*96 + c] = so / sl;
}

// ---------------- LayerNorm ----------------
__global__ void ln_kernel(float* __restrict__ t, const float* __restrict__ delta,
                          const float* __restrict__ g, const float* __restrict__ b)
{
    __shared__ float sr[96];
    int i = blockIdx.x, c = threadIdx.x;
    float x = t[(size_t)i*96 + c] + delta[(size_t)i*96 + c];
    sr[c] = x;
    __syncthreads();
    for (int s = 64; s > 0; s >>= 1) { if (c < s && c + s < 96) sr[c] += sr[c+s]; __syncthreads(); }
    float mu = sr[0] / 96.f;
    __syncthreads();
    float d = x - mu;
    sr[c] = d * d;
    __syncthreads();
    for (int s = 64; s > 0; s >>= 1) { if (c < s && c + s < 96) sr[c] += sr[c+s]; __syncthreads(); }
    float var = sr[0] / 96.f;
    t[(size_t)i*96 + c] = d * rsqrtf(var + 1e-5f) * g[c] + b[c];
}

// ---------------- GCN propagation ----------------
__global__ void k_deg_init() { int i = blockIdx.x*blockDim.x + threadIdx.x; if (i < MM) g_deg[i] = 1.f; }
__global__ void k_deg_acc(const int* __restrict__ ei) {
    int e = blockIdx.x*blockDim.x + threadIdx.x;
    if (e < EE) atomicAdd(&g_deg[ei[EE + e]], 1.f);
}
__global__ void k_nrm() { int i = blockIdx.x*blockDim.x + threadIdx.x; if (i < MM) g_nrm[i] = rsqrtf(g_deg[i]); }
__global__ void k_prop_init(const float* __restrict__ h, int F) {
    int idx = blockIdx.x*blockDim.x + threadIdx.x;
    if (idx < MM * F) g_agg[idx] = h[idx] * g_nrm[idx / F];
}
__global__ void k_prop_edge(const float* __restrict__ h, const int* __restrict__ ei, int F) {
    int idx = blockIdx.x*blockDim.x + threadIdx.x;
    if (idx < EE * F) {
        int e = idx / F, f = idx % F;
        int s = ei[e], d = ei[EE + e];
        atomicAdd(&g_agg[(size_t)d * F + f], h[(size_t)s * F + f] * g_nrm[s]);
    }
}
__global__ void k_prop_scale(int F) {
    int idx = blockIdx.x*blockDim.x + threadIdx.x;
    if (idx < MM * F) g_agg[idx] *= g_nrm[idx / F];
}

// ---------------- Sinkhorn setup ----------------
__global__ void k_bins(const float* __restrict__ binp) {
    int i = blockIdx.x*blockDim.x + threadIdx.x;
    if (i < MP1) {
        float bl = binp[0] / LAMBDA;
        g_Cp[(size_t)i*CPLD + (MP1-1)] = bl;
        g_Cp[(size_t)(MP1-1)*CPLD + i] = bl;
    }
}
__global__ void transpose_kernel() {
    __shared__ float tile[32][33];
    int bx = blockIdx.x * 32, by = blockIdx.y * 32;
    int tx = threadIdx.x, ty = threadIdx.y;
    #pragma unroll
    for (int r = 0; r < 32; r += 8) {
        int y = by + ty + r, x = bx + tx;
        if (y < MP1 && x < MP1) tile[ty + r][tx] = g_Cp[(size_t)y*CPLD + x];
    }
    __syncthreads();
    #pragma unroll
    for (int r = 0; r < 32; r += 8) {
        int y = bx + ty + r, x = by + tx;
        if (y < MP1 && x < MP1) g_CpT[(size_t)y*CPLD + x] = tile[tx][ty + r];
    }
}
__global__ void rowmax_kernel(const float* __restrict__ Mx, float* __restrict__ out) {
    int wid = threadIdx.x >> 5, lane = threadIdx.x & 31;
    int r = blockIdx.x * 8 + wid;
    if (r >= MP1) return;
    const float4* row = (const float4*)(Mx + (size_t)r * CPLD);
    float m = -1e30f;
    #pragma unroll
    for (int k0 = 0; k0 < 16; k0++) {
        float4 a = row[lane + 32*k0];
        m = fmaxf(m, fmaxf(fmaxf(a.x, a.y), fmaxf(a.z, a.w)));
    }
    if (lane == 0) m = fmaxf(m, Mx[(size_t)r*CPLD + 2048]);
    #pragma unroll
    for (int off = 16; off; off >>= 1) m = fmaxf(m, __shfl_xor_sync(0xffffffffu, m, off));
    if (lane == 0) out[r] = m;
}
__global__ void expsub_kernel(const float* __restrict__ Mx, const float* __restrict__ mx,
                              float* __restrict__ P) {
    int j = blockIdx.x * 256 + threadIdx.x;
    int r = blockIdx.y;
    if (j < CPLD)
        P[(size_t)r*CPLD + j] = (j < MP1) ? __expf(Mx[(size_t)r*CPLD + j] - mx[r]) : 0.f;
}
__global__ void k_sink_init() {
    int i = blockIdx.x*blockDim.x + threadIdx.x;
    if (i < CPLD) {
        float norm = -logf((float)(MM + NN));
        bool pad = (i >= MP1);
        g_eu[i] = pad ? 0.f : 1.f;
        g_ev[i] = pad ? 0.f : 1.f;
        if (!pad) {
            float lmu = (i < MM) ? norm : (logf((float)NN) + norm);
            float lnu = (i < NN) ? norm : (logf((float)MM) + norm);
            float a = lmu - g_rmax[i];
            float b = lnu - g_cmax[i];
            g_lmmu[i] = a; g_emu[i] = __expf(a);
            g_lmmv[i] = b; g_emv[i] = __expf(b);
            g_u[i] = 0.f; g_v[i] = 0.f;
        }
    }
}

// ---------------- Sinkhorn GEMV v7: bulk-copy (TMA path) rows+ev into smem ----------------
// 257 blocks x 256 thr, dynamic smem: 8 rows (8224B each) + ev (8224B) + mbarrier.
__global__ void __launch_bounds__(256) gemv6(const float* __restrict__ Pm,
                                             const float* __restrict__ evin,
                                             const float* __restrict__ emarg,
                                             const float* __restrict__ lmm,
                                             float* __restrict__ evout,
                                             float* __restrict__ logout)
{
    extern __shared__ float smem[];
    float* srow = smem;                 // 8 * CPLD floats
    float* sev  = smem + 8*CPLD;        // CPLD floats
    unsigned long long* mbp = (unsigned long long*)(smem + 9*CPLD);
    unsigned mbar = smem_u32(mbp);
    int tid = threadIdx.x, lane = tid & 31, warp = tid >> 5;
    int r0 = blockIdx.x * 8;
    int nrows = min(8, MP1 - r0);

    if (tid == 0) mbar_init(mbar, 1);
    __syncthreads();
    if (tid == 0) {
        unsigned tx = (unsigned)(nrows + 1) * (CPLD*4);
        mbar_expect(mbar, tx);
        bulk_g2s(smem_u32(sev), evin, CPLD*4, mbar);
        for (int i = 0; i < nrows; i++)
            bulk_g2s(smem_u32(srow + i*CPLD), Pm + (size_t)(r0 + i)*CPLD, CPLD*4, mbar);
    }
    mbar_wait0(mbar);

    int r = r0 + warp;
    if (r >= MP1) return;
    const float4* row4 = (const float4*)(srow + warp*CPLD);
    const float4* sev4 = (const float4*)sev;
    float a0 = 0.f, a1 = 0.f, a2 = 0.f, a3 = 0.f;
    #pragma unroll
    for (int k = 0; k < 16; k += 4) {
        float4 p0 = row4[lane + 32*(k+0)], e0 = sev4[lane + 32*(k+0)];
        float4 p1 = row4[lane + 32*(k+1)], e1 = sev4[lane + 32*(k+1)];
        float4 p2 = row4[lane + 32*(k+2)], e2 = sev4[lane + 32*(k+2)];
        float4 p3 = row4[lane + 32*(k+3)], e3 = sev4[lane + 32*(k+3)];
        a0 += p0.x*e0.x + p0.y*e0.y + p0.z*e0.z + p0.w*e0.w;
        a1 += p1.x*e1.x + p1.y*e1.y + p1.z*e1.z + p1.w*e1.w;
        a2 += p2.x*e2.x + p2.y*e2.y + p2.z*e2.z + p2.w*e2.w;
        a3 += p3.x*e3.x + p3.y*e3.y + p3.z*e3.z + p3.w*e3.w;
    }
    if (lane == 0) {                    // float4 slots 512,513 (cols 2048..2055, pads 0)
        float4 p = row4[512], e = sev4[512];
        a0 += p.x*e.x + p.y*e.y + p.z*e.z + p.w*e.w;
        p = row4[513]; e = sev4[513];
        a1 += p.x*e.x + p.y*e.y + p.z*e.z + p.w*e.w;
    }
    float acc = (a0 + a1) + (a2 + a3);
    #pragma unroll
    for (int off = 16; off; off >>= 1) acc += __shfl_xor_sync(0xffffffffu, acc, off);
    if (lane == 0) {
        evout[r]  = emarg[r] / acc;
        logout[r] = lmm[r] - __logf(acc);
    }
}

// ---------------- outputs ----------------
__global__ void __launch_bounds__(256) k_scores_row(float* __restrict__ out,
                                                    float* __restrict__ ent_out)
{
    __shared__ float sv[256]; __shared__ int si[256]; __shared__ float se[256];
    int i = blockIdx.x, tid = threadIdx.x;
    const float norm = -8.317766166719343f;
    float ui = g_u[i];
    bool dorow = (i < MM);
    float bv = -1e30f; int bi = 0; float ent = 0.f;
    for (int j = tid; j < MP1; j += 256) {
        float x = g_Cp[(size_t)i*CPLD + j] + ui + g_v[j] - norm;
        out[(size_t)i*MP1 + j] = x;
        if (dorow && j < NN) {
            if (x > bv) { bv = x; bi = j; }
            ent += x * __expf(x);
        }
    }
    if (!dorow) return;
    sv[tid] = bv; si[tid] = bi; se[tid] = ent; __syncthreads();
    for (int s = 128; s > 0; s >>= 1) {
        if (tid < s) {
            if (sv[tid+s] > sv[tid] || (sv[tid+s] == sv[tid] && si[tid+s] < si[tid])) {
                sv[tid] = sv[tid+s]; si[tid] = si[tid+s];
            }
            se[tid] += se[tid+s];
        }
        __syncthreads();
    }
    if (tid == 0) { g_v0[i] = sv[0]; g_i0[i] = si[0]; ent_out[i] = se[0]; }
}
__global__ void k_colstat() {
    __shared__ float sv[256]; __shared__ int si[256];
    int j = blockIdx.x, tid = threadIdx.x;
    const float norm = -8.317766166719343f;
    float vj = g_v[j];
    float bv = -1e30f; int bi = 0;
    for (int i = tid; i < MM; i += 256) {
        float x = g_CpT[(size_t)j*CPLD + i] + g_u[i] + vj - norm;
        if (x > bv) { bv = x; bi = i; }
    }
    sv[tid] = bv; si[tid] = bi; __syncthreads();
    for (int s = 128; s > 0; s >>= 1) {
        if (tid < s) {
            if (sv[tid+s] > sv[tid] || (sv[tid+s] == sv[tid] && si[tid+s] < si[tid])) {
                sv[tid] = sv[tid+s]; si[tid] = si[tid+s];
            }
        }
        __syncthreads();
    }
    if (tid == 0) { g_v1[j] = sv[0]; g_i1[j] = si[0]; }
}
__global__ void k_mutual0(float* __restrict__ ms0_out) {
    int i = blockIdx.x*blockDim.x + threadIdx.x;
    if (i < MM) {
        int j = g_i0[i];
        float val = (g_i1[j] == i) ? __expf(g_v0[i]) : 0.f;
        g_ms0[i] = val;
        ms0_out[i] = val;
    }
}
__global__ void k_mutual1(float* __restrict__ ms1_out) {
    int j = blockIdx.x*blockDim.x + threadIdx.x;
    if (j < NN) {
        int i = g_i1[j];
        ms1_out[j] = (g_i0[i] == j) ? g_ms0[i] : 0.f;
    }
}

// ---------------- host side ----------------
static float* sym(const void* p) { return (float*)p; }

extern "C" void kernel_launch(void* const* d_in, const int* in_sizes, int n_in,
                              void* d_out, int out_size)
{
    const float* x        = (const float*)d_in[0];
    const int*   ei       = (const int*)  d_in[1];
    const float* devfeat  = (const float*)d_in[2];
    const float* gnn_w1   = (const float*)d_in[3];
    const float* gnn_b1   = (const float*)d_in[4];
    const float* gnn_w2   = (const float*)d_in[5];
    const float* gnn_b2   = (const float*)d_in[6];
    const float* sa_w     = (const float*)d_in[7];
    const float* sa_b     = (const float*)d_in[8];
    const float* sa_ow    = (const float*)d_in[9];
    const float* sa_ob    = (const float*)d_in[10];
    const float* ca_w     = (const float*)d_in[11];
    const float* ca_b     = (const float*)d_in[12];
    const float* ca_ow    = (const float*)d_in[13];
    const float* ca_ob    = (const float*)d_in[14];
    const float* ln_g     = (const float*)d_in[15];
    const float* ln_b     = (const float*)d_in[16];
    const float* ff_w1    = (const float*)d_in[17];
    const float* ff_b1    = (const float*)d_in[18];
    const float* ff_w2    = (const float*)d_in[19];
    const float* ff_b2    = (const float*)d_in[20];
    const float* mf_w     = (const float*)d_in[21];
    const float* mf_b     = (const float*)d_in[22];
    const float* bin      = (const float*)d_in[23];
    float* out = (float*)d_out;

    void *pv;
    cudaGetSymbolAddress(&pv, g_Cp);    float* p_Cp    = sym(pv);
    cudaGetSymbolAddress(&pv, g_CpT);   float* p_CpT   = sym(pv);
    cudaGetSymbolAddress(&pv, g_P);     float* p_P     = sym(pv);
    cudaGetSymbolAddress(&pv, g_QT);    float* p_QT    = sym(pv);
    cudaGetSymbolAddress(&pv, g_rmax);  float* p_rmax  = sym(pv);
    cudaGetSymbolAddress(&pv, g_cmax);  float* p_cmax  = sym(pv);
    cudaGetSymbolAddress(&pv, g_t);     float* p_t     = sym(pv);
    cudaGetSymbolAddress(&pv, g_qkv);   float* p_qkv   = sym(pv);
    cudaGetSymbolAddress(&pv, g_attno); float* p_attno = sym(pv);
    cudaGetSymbolAddress(&pv, g_attp);  float* p_attp  = sym(pv);
    cudaGetSymbolAddress(&pv, g_attlp); float* p_attlp = sym(pv);
    cudaGetSymbolAddress(&pv, g_proj);  float* p_proj  = sym(pv);
    cudaGetSymbolAddress(&pv, g_ff1);   float* p_ff1   = sym(pv);
    cudaGetSymbolAddress(&pv, g_cg);    float* p_cg    = sym(pv);
    cudaGetSymbolAddress(&pv, g_match); float* p_match = sym(pv);
    cudaGetSymbolAddress(&pv, g_agg);   float* p_agg   = sym(pv);
    cudaGetSymbolAddress(&pv, g_h);     float* p_h     = sym(pv);
    cudaGetSymbolAddress(&pv, g_eu);    float* p_eu    = sym(pv);
    cudaGetSymbolAddress(&pv, g_ev);    float* p_ev    = sym(pv);
    cudaGetSymbolAddress(&pv, g_emu);   float* p_emu   = sym(pv);
    cudaGetSymbolAddress(&pv, g_emv);   float* p_emv   = sym(pv);
    cudaGetSymbolAddress(&pv, g_lmmu);  float* p_lmmu  = sym(pv);
    cudaGetSymbolAddress(&pv, g_lmmv);  float* p_lmmv  = sym(pv);
    cudaGetSymbolAddress(&pv, g_u);     float* p_u     = sym(pv);
    cudaGetSymbolAddress(&pv, g_v);     float* p_v     = sym(pv);

    cudaFuncSetAttribute(gemv6, cudaFuncAttributeMaxDynamicSharedMemorySize, G6_SMEM);

    auto gemm = [&](const float* A, const float* B, const float* bias, float* C,
                    int Mm, int Nn, int Kk, int ldc, int transB, int mode, float alpha) {
        if (Nn <= 512 && (Mm % 32) == 0 && (Nn % 32) == 0) {
            dim3 grid(Nn / 32, Mm / 32);
            gemm_small<<<grid, 256>>>(A, B, bias, C, Mm, Nn, Kk, ldc, transB, mode, alpha);
        } else {
            dim3 grid((Nn + 63) / 64, (Mm + 127) / 128);
            gemm_kernel<<<grid, 256>>>(A, B, bias, C, Mm, Nn, Kk, ldc, transB, mode, alpha);
        }
    };

    int sgrid = (MP1 + 7) / 8;   // 257 blocks

    // ---- ncu probes (profiled launch = gemv6; state re-initialized later) ----
    for (int p = 0; p < 8; p++)
        gemv6<<<sgrid, 256, G6_SMEM>>>(p_P, p_ev, p_emu, p_lmmu, p_eu, p_u);

    // ---- GCN ----
    k_deg_init<<<(MM+255)/256, 256>>>();
    k_deg_acc<<<(EE+255)/256, 256>>>(ei);
    k_nrm<<<(MM+255)/256, 256>>>();

    k_prop_init <<<(MM*DIN+255)/256, 256>>>(x, DIN);
    k_prop_edge <<<(EE*DIN+255)/256, 256>>>(x, ei, DIN);
    k_prop_scale<<<(MM*DIN+255)/256, 256>>>(DIN);
    gemm(p_agg, gnn_w1, gnn_b1, p_h, MM, HID, DIN, HID, 1, 0, 1.f);

    k_prop_init <<<(MM*HID+255)/256, 256>>>(p_h, HID);
    k_prop_edge <<<(EE*HID+255)/256, 256>>>(p_h, ei, HID);
    k_prop_scale<<<(MM*HID+255)/256, 256>>>(HID);
    gemm(p_agg, gnn_w2, gnn_b2, p_cg, MM, DD, HID, DD, 1, 0, 1.f);

    // ---- transformer ----
    cudaMemcpyAsync(p_t, devfeat, (size_t)MM*DD*sizeof(float), cudaMemcpyDeviceToDevice);
    dim3 agrid(AKC, NHH, MM/256);
    for (int l = 0; l < LL; l++) {
        gemm(p_t, sa_w + (size_t)l*288*96, sa_b + l*288, p_qkv, MM, 288, 96, 288, 0, 0, 1.f);
        attn2_kernel<<<agrid, 256>>>(p_qkv, p_attp, p_attlp);
        attn2_norm<<<MM, 96>>>(p_attp, p_attlp, p_attno);
        gemm(p_attno, sa_ow + (size_t)l*96*96, sa_ob + l*96, p_proj, MM, 96, 96, 96, 0, 0, 1.f);
        ln_kernel<<<MM, 96>>>(p_t, p_proj, ln_g + (l*3+0)*96, ln_b + (l*3+0)*96);
        gemm(p_t,  ca_w + (size_t)l*288*96,         ca_b + l*288,      p_qkv,      MM,  96, 96, 288, 0, 0, 1.f);
        gemm(p_cg, ca_w + (size_t)l*288*96 + 96*96, ca_b + l*288 + 96, p_qkv + 96, MM, 192, 96, 288, 0, 0, 1.f);
        attn2_kernel<<<agrid, 256>>>(p_qkv, p_attp, p_attlp);
        attn2_norm<<<MM, 96>>>(p_attp, p_attlp, p_attno);
        gemm(p_attno, ca_ow + (size_t)l*96*96, ca_ob + l*96, p_proj, MM, 96, 96, 96, 0, 0, 1.f);
        ln_kernel<<<MM, 96>>>(p_t, p_proj, ln_g + (l*3+1)*96, ln_b + (l*3+1)*96);
        gemm(p_t,   ff_w1 + (size_t)l*256*96, ff_b1 + l*256, p_ff1,  MM, 256,  96, 256, 0, 1, 1.f);
        gemm(p_ff1, ff_w2 + (size_t)l*96*256, ff_b2 + l*96,  p_proj, MM,  96, 256,  96, 0, 0, 1.f);
        ln_kernel<<<MM, 96>>>(p_t, p_proj, ln_g + (l*3+2)*96, ln_b + (l*3+2)*96);
    }

    // ---- cost matrix + bins + transpose + exp-precompute ----
    gemm(p_t, mf_w, mf_b, p_match, MM, 96, 96, 96, 1, 0, 1.f);
    float alpha = 1.f / (sqrtf(96.f) * LAMBDA);
    gemm(p_cg, p_match, 0, p_Cp, MM, NN, 96, CPLD, 0, 2, alpha);
    k_bins<<<(MP1+255)/256, 256>>>(bin);
    transpose_kernel<<<dim3(65, 65), dim3(32, 8)>>>();
    rowmax_kernel<<<(MP1+7)/8, 256>>>(p_Cp,  p_rmax);
    rowmax_kernel<<<(MP1+7)/8, 256>>>(p_CpT, p_cmax);
    expsub_kernel<<<dim3((CPLD+255)/256, MP1), 256>>>(p_Cp,  p_rmax, p_P);
    expsub_kernel<<<dim3((CPLD+255)/256, MP1), 256>>>(p_CpT, p_cmax, p_QT);
    k_sink_init<<<(CPLD+255)/256, 256>>>();

    // ---- Sinkhorn ----
    for (int it = 0; it < SINK_ITERS; it++) {
        gemv6<<<sgrid, 256, G6_SMEM>>>(p_P,  p_ev, p_emu, p_lmmu, p_eu, p_u);
        gemv6<<<sgrid, 256, G6_SMEM>>>(p_QT, p_eu, p_emv, p_lmmv, p_ev, p_v);
    }

    // ---- outputs ----
    size_t off_ent = (size_t)MP1 * MP1;
    k_scores_row<<<MP1, 256>>>(out, out + off_ent);
    k_colstat<<<NN, 256>>>();
    k_mutual0<<<(MM+255)/256, 256>>>(out + off_ent + MM);
    k_mutual1<<<(NN+255)/256, 256>>>(out + off_ent + MM + NN);
}